// round 12
// baseline (speedup 1.0000x reference)
#include <cuda_runtime.h>

// MultiScaleProcessor: images [64,256,256,3] f32 ->
// out [64, 4(scales 32/64/128/256), 256, 256, 3] f32.
//
// Two-phase split:
//   Kernel B (first): bilinear-interp INTERIORS of scales 32/64/128 only.
//     Does the one compulsory cold DRAM read of the input (~50MB), writes
//     only 16.8MB. Leaves input resident in L2 (50MB < 126MB).
//   Kernel A (second): pure streaming — native-res copy plane (reads hit
//     L2) + all pad zeros. 184.5MB of __stcs stores, near-zero DRAM reads.
//
// All interior segments are 16B-aligned: pad p*3 floats = 336/288/192,
// all divisible by 4; segment lengths s*3/4 = 96/48/24 float4.
// Kernel B packs 96 active vec4s per block: 1 row @s=128, 2 @s=64, 4 @s=32.

#define IMG_H 256
#define IMG_W 256
#define C 3
#define FLOATS_PER_ROW (IMG_W * C)                 // 768
#define VEC_PER_ROW (FLOATS_PER_ROW / 4)           // 192
#define FLOATS_PER_PLANE (IMG_H * FLOATS_PER_ROW)  // 196608
#define VEC_PER_PLANE (FLOATS_PER_PLANE / 4)       // 49152

// ───────────────────────── Kernel B: interp interiors ─────────────────────
// grid (168 row-groups, 64 images):
//   g < 128: sidx=2, 1 row  (96 vec4/row)
//   g < 160: sidx=1, 2 rows (48 vec4/row)
//   else   : sidx=0, 4 rows (24 vec4/row)
__global__ __launch_bounds__(96) void interp_kernel(const float* __restrict__ in,
                                                    float* __restrict__ out) {
    const int g = blockIdx.x;
    const int b = blockIdx.y;
    const int t = threadIdx.x;

    int sidx, yi, lane;
    if (g < 128)      { sidx = 2; yi = g;                       lane = t;      }
    else if (g < 160) { sidx = 1; yi = (g - 128) * 2 + t / 48;  lane = t % 48; }
    else              { sidx = 0; yi = (g - 160) * 4 + t / 24;  lane = t % 24; }

    const int s = 32 << sidx;
    const int p = (IMG_H - s) >> 1;
    const int startVec = (p * 3) >> 2;             // 48 / 72 / 84

    const float* __restrict__ img = in + (size_t)b * FLOATS_PER_PLANE;

    const float step = 255.0f / (float)(s - 1);
    const float fy = (float)yi * step;
    const int   y0 = (int)fy;
    const float wy = fy - (float)y0;
    const int   y1 = min(y0 + 1, IMG_H - 1);
    const float omy = 1.0f - wy;
    const float* __restrict__ row0 = img + y0 * FLOATS_PER_ROW;
    const float* __restrict__ row1 = img + y1 * FLOATS_PER_ROW;

    // Per-lane x mapping: local float lf = lane*4+k within the interior
    // segment (segment starts at channel 0 of pixel p).
    int   i00[4], i01[4];
    float wxv[4];
    {
        int lf = lane * 4;
        #pragma unroll
        for (int k = 0; k < 4; ++k, ++lf) {
            const int xi = lf / 3;                 // interior pixel x
            const int c  = lf - xi * 3;
            const float fx = (float)xi * step;
            const int   x0 = (int)fx;
            wxv[k] = fx - (float)x0;
            const int x1 = min(x0 + 1, IMG_W - 1);
            i00[k] = x0 * C + c;
            i01[k] = x1 * C + c;
        }
    }

    float v00[4], v01[4], v10[4], v11[4];
    #pragma unroll
    for (int k = 0; k < 4; ++k) v00[k] = __ldg(&row0[i00[k]]);
    #pragma unroll
    for (int k = 0; k < 4; ++k) v01[k] = __ldg(&row0[i01[k]]);
    #pragma unroll
    for (int k = 0; k < 4; ++k) v10[k] = __ldg(&row1[i00[k]]);
    #pragma unroll
    for (int k = 0; k < 4; ++k) v11[k] = __ldg(&row1[i01[k]]);

    float res[4];
    #pragma unroll
    for (int k = 0; k < 4; ++k) {
        const float wx  = wxv[k];
        const float omx = 1.0f - wx;
        const float top = v00[k] * omx + v01[k] * wx;
        const float bot = v10[k] * omx + v11[k] * wx;
        res[k] = top * omy + bot * wy;
    }

    float4* __restrict__ orow = reinterpret_cast<float4*>(out)
        + ((size_t)(b * 4 + sidx) * IMG_H + (p + yi)) * VEC_PER_ROW;
    __stcs(&orow[startVec + lane], make_float4(res[0], res[1], res[2], res[3]));
}

// ───────────────────── Kernel A: copy plane + pad zeros ───────────────────
// grid (256 rows, 4 scales, 64 images), block 192, one float4/thread.
__global__ __launch_bounds__(VEC_PER_ROW) void stream_kernel(const float* __restrict__ in,
                                                             float* __restrict__ out) {
    const int y    = blockIdx.x;
    const int sidx = blockIdx.y;
    const int b    = blockIdx.z;
    const int vx   = threadIdx.x;

    float4* __restrict__ orow = reinterpret_cast<float4*>(out)
        + ((size_t)(b * 4 + sidx) * IMG_H + y) * VEC_PER_ROW;

    if (sidx == 3) {
        // Native-resolution copy; reads are L2-warm from interp_kernel.
        const float4 v = reinterpret_cast<const float4*>(in)
            [(size_t)b * VEC_PER_PLANE + (size_t)y * VEC_PER_ROW + vx];
        __stcs(&orow[vx], v);
        return;
    }

    const int s = 32 << sidx;
    const int p = (IMG_H - s) >> 1;
    const int yi = y - p;
    const float4 z = make_float4(0.f, 0.f, 0.f, 0.f);

    if ((unsigned)yi >= (unsigned)s) {
        __stcs(&orow[vx], z);                      // full pad row
        return;
    }
    // Interior row: zero only the side-pad vec4s; interior written by B.
    const int startVec = (p * 3) >> 2;
    const int endVec   = startVec + ((s * 3) >> 2);
    if (vx < startVec || vx >= endVec)
        __stcs(&orow[vx], z);
}

extern "C" void kernel_launch(void* const* d_in, const int* in_sizes, int n_in,
                              void* d_out, int out_size) {
    const float* images = (const float*)d_in[0];
    float* out = (float*)d_out;

    // Phase 1: interiors (cold input read, warms L2).
    dim3 gB(168, 64);
    interp_kernel<<<gB, 96>>>(images, out);

    // Phase 2: pure streaming (copy + pad zeros).
    dim3 gA(IMG_H, 4, 64);
    stream_kernel<<<gA, VEC_PER_ROW>>>(images, out);
}